// round 5
// baseline (speedup 1.0000x reference)
#include <cuda_runtime.h>
#include <cuda_fp16.h>
#include <cstdint>

// GeluAvgEmbed: out[cell] = dot(gelu(mean_t W[x[cell,t]]), w_pred) + b_pred
// B,R,C,T = 8,100,64,32 ; D = 128 ; VOCAB = 32000
//
// R2: fp16 gather. Prologue kernel converts W (f32, 16.4MB) -> fp16 scratch
// (8.2MB, __device__ global). Gather kernel: one warp per cell, TWO rows per
// warp-load (lanes 0-15 / 16-31 each own 8 dims of one row via a 16B LDG.128).
// Accumulation in fp32; exact-erf GELU; fp32 dot with w_pred.

#define TOKENS 32
#define DIMS   128
#define VOCAB  32000
#define FULL_MASK 0xffffffffu

// fp16 copy of the embedding table: 32000 * 128 * 2B = 8.192 MB
__device__ __half W_half[(size_t)VOCAB * DIMS];

__global__ __launch_bounds__(256) void convert_w_kernel(
    const float* __restrict__ W, int n4)
{
    int i = blockIdx.x * blockDim.x + threadIdx.x;
    if (i >= n4) return;
    float4 v = reinterpret_cast<const float4*>(W)[i];
    __half2 h0 = __floats2half2_rn(v.x, v.y);
    __half2 h1 = __floats2half2_rn(v.z, v.w);
    __half2* dst = reinterpret_cast<__half2*>(W_half) + 2 * (size_t)i;
    dst[0] = h0;
    dst[1] = h1;
}

__global__ __launch_bounds__(256) void gelu_avg_embed_kernel(
    const int*   __restrict__ x,        // [n_cells * 32]
    const float* __restrict__ w_pred,   // [128]
    const float* __restrict__ b_pred,   // [1]
    float*       __restrict__ out,      // [n_cells]
    int n_cells)
{
    const int gwarp = (blockIdx.x * blockDim.x + threadIdx.x) >> 5;
    const int lane  = threadIdx.x & 31;
    if (gwarp >= n_cells) return;

    // Lane t holds token t's vocab index (coalesced 128B load of 32 ints).
    const int my_idx = x[gwarp * TOKENS + lane];

    const int half_sel = lane >> 4;   // 0: even token of the pair, 1: odd
    const int sub      = lane & 15;   // which 8-dim slice of the row

    float acc[8];
    #pragma unroll
    for (int k = 0; k < 8; ++k) acc[k] = 0.f;

    #pragma unroll
    for (int i = 0; i < TOKENS / 2; ++i) {
        const int row = __shfl_sync(FULL_MASK, my_idx, 2 * i + half_sel);
        const uint4 v = *reinterpret_cast<const uint4*>(
            W_half + (size_t)row * DIMS + sub * 8);

        float2 f;
        f = __half22float2(*reinterpret_cast<const __half2*>(&v.x));
        acc[0] += f.x; acc[1] += f.y;
        f = __half22float2(*reinterpret_cast<const __half2*>(&v.y));
        acc[2] += f.x; acc[3] += f.y;
        f = __half22float2(*reinterpret_cast<const __half2*>(&v.z));
        acc[4] += f.x; acc[5] += f.y;
        f = __half22float2(*reinterpret_cast<const __half2*>(&v.w));
        acc[6] += f.x; acc[7] += f.y;
    }

    // Fold the odd-token half (lanes 16-31) into the even-token half (0-15).
    #pragma unroll
    for (int k = 0; k < 8; ++k)
        acc[k] += __shfl_down_sync(FULL_MASK, acc[k], 16);

    // Lanes 0-15 now hold full token sums for dims [8*sub, 8*sub+8).
    const float inv_t = 1.0f / (float)TOKENS;
    const float kInvSqrt2 = 0.70710678118654752440f;

    const float4 w0 = *reinterpret_cast<const float4*>(w_pred + sub * 8);
    const float4 w1 = *reinterpret_cast<const float4*>(w_pred + sub * 8 + 4);
    const float wv[8] = { w0.x, w0.y, w0.z, w0.w, w1.x, w1.y, w1.z, w1.w };

    float dot = 0.f;
    #pragma unroll
    for (int k = 0; k < 8; ++k) {
        const float p = acc[k] * inv_t;
        const float g = 0.5f * p * (1.0f + erff(p * kInvSqrt2));
        dot += g * wv[k];
    }

    // Reduce over the 16 active lanes.
    #pragma unroll
    for (int off = 8; off > 0; off >>= 1)
        dot += __shfl_down_sync(FULL_MASK, dot, off);

    if (lane == 0)
        out[gwarp] = dot + b_pred[0];
}

extern "C" void kernel_launch(void* const* d_in, const int* in_sizes, int n_in,
                              void* d_out, int out_size)
{
    const int*   x      = (const int*)  d_in[0];  // [8,100,64,32] int32
    const float* W      = (const float*)d_in[1];  // [32000,128]  f32
    const float* w_pred = (const float*)d_in[2];  // [1,128]      f32
    const float* b_pred = (const float*)d_in[3];  // [1]          f32
    float*       out    = (float*)d_out;          // [8,100,64]   f32

    // 1) Convert W to fp16 scratch (re-done every launch: deterministic).
    const int n4 = VOCAB * DIMS / 4;              // 1,024,000 float4s
    convert_w_kernel<<<(n4 + 255) / 256, 256>>>(W, n4);

    // 2) Gather + pool + GELU + dot.
    const int n_cells = out_size;                  // 51200
    const int warps_per_block = 8;                 // 256 threads
    const int blocks = (n_cells + warps_per_block - 1) / warps_per_block;
    gelu_avg_embed_kernel<<<blocks, 256>>>(x, w_pred, b_pred, out, n_cells);
}

// round 9
// speedup vs baseline: 1.8191x; 1.8191x over previous
#include <cuda_runtime.h>
#include <cuda_fp16.h>
#include <cstdint>

// GeluAvgEmbed: out[cell] = dot(gelu(mean_t W[x[cell,t]]), w_pred) + b_pred
// B,R,C,T = 8,100,64,32 ; D = 128 ; VOCAB = 32000
//
// R8 (= R6 with compile fix): fp16 table + native half2 accumulation.
// One warp per cell, one token per iteration. Lane owns dims [4l,4l+4)
// (one LDG.64 = 2 half2). 4-way-split HADD2 accumulators keep each half
// rounding chain at 8 adds; splits combined in fp32 before GELU.

#define TOKENS 32
#define DIMS   128
#define VOCAB  32000
#define FULL_MASK 0xffffffffu

// fp16 copy of the embedding table: 32000 * 128 * 2B = 8.192 MB
__device__ __half2 W_half[(size_t)VOCAB * DIMS / 2];

__global__ __launch_bounds__(256) void convert_w_kernel(
    const float* __restrict__ W, int n8)
{
    int i = blockIdx.x * blockDim.x + threadIdx.x;
    if (i >= n8) return;
    const float4* src = reinterpret_cast<const float4*>(W) + 2 * (size_t)i;
    float4 v0 = src[0];
    float4 v1 = src[1];
    __half2* dst = W_half + 4 * (size_t)i;
    dst[0] = __floats2half2_rn(v0.x, v0.y);
    dst[1] = __floats2half2_rn(v0.z, v0.w);
    dst[2] = __floats2half2_rn(v1.x, v1.y);
    dst[3] = __floats2half2_rn(v1.z, v1.w);
}

__global__ __launch_bounds__(256) void gelu_avg_embed_kernel(
    const int*   __restrict__ x,        // [n_cells * 32]
    const float* __restrict__ w_pred,   // [128]
    const float* __restrict__ b_pred,   // [1]
    float*       __restrict__ out,      // [n_cells]
    int n_cells)
{
    const int gwarp = (blockIdx.x * blockDim.x + threadIdx.x) >> 5;
    const int lane  = threadIdx.x & 31;
    if (gwarp >= n_cells) return;

    // Lane t holds token t's vocab index (coalesced 128B load of 32 ints).
    const int my_idx = x[gwarp * TOKENS + lane];

    // 4-way split accumulators: bank (t & 3), each half2 covers 2 dims.
    __half2 accA[4];   // dims 4l, 4l+1
    __half2 accB[4];   // dims 4l+2, 4l+3
    #pragma unroll
    for (int k = 0; k < 4; ++k) {
        accA[k] = __float2half2_rn(0.f);
        accB[k] = __float2half2_rn(0.f);
    }

    // Lane l owns half2 pair at column offset 2l, 2l+1 (i.e. dims 4l..4l+3).
    const __half2* base = W_half + 2 * (size_t)lane;

    #pragma unroll
    for (int t = 0; t < TOKENS; ++t) {
        const int row = __shfl_sync(FULL_MASK, my_idx, t);
        // 8-byte vector load of two half2s.
        const __half2* p = base + (size_t)row * (DIMS / 2);
        float2 raw = *reinterpret_cast<const float2*>(p);  // bit-carrier
        __half2 vA = *reinterpret_cast<const __half2*>(&raw.x);
        __half2 vB = *reinterpret_cast<const __half2*>(&raw.y);
        accA[t & 3] = __hadd2(accA[t & 3], vA);
        accB[t & 3] = __hadd2(accB[t & 3], vB);
    }

    // Combine the 4 splits in fp32.
    float s0 = 0.f, s1 = 0.f, s2 = 0.f, s3 = 0.f;
    #pragma unroll
    for (int k = 0; k < 4; ++k) {
        float2 fa = __half22float2(accA[k]);
        float2 fb = __half22float2(accB[k]);
        s0 += fa.x; s1 += fa.y; s2 += fb.x; s3 += fb.y;
    }

    const float inv_t = 1.0f / (float)TOKENS;
    const float kInvSqrt2 = 0.70710678118654752440f;

    float p0 = s0 * inv_t, p1 = s1 * inv_t, p2 = s2 * inv_t, p3 = s3 * inv_t;
    float g0 = 0.5f * p0 * (1.0f + erff(p0 * kInvSqrt2));
    float g1 = 0.5f * p1 * (1.0f + erff(p1 * kInvSqrt2));
    float g2 = 0.5f * p2 * (1.0f + erff(p2 * kInvSqrt2));
    float g3 = 0.5f * p3 * (1.0f + erff(p3 * kInvSqrt2));

    const float4 wv = *reinterpret_cast<const float4*>(w_pred + lane * 4);
    float dot = g0 * wv.x + g1 * wv.y + g2 * wv.z + g3 * wv.w;

    #pragma unroll
    for (int off = 16; off > 0; off >>= 1)
        dot += __shfl_down_sync(FULL_MASK, dot, off);

    if (lane == 0)
        out[gwarp] = dot + b_pred[0];
}

extern "C" void kernel_launch(void* const* d_in, const int* in_sizes, int n_in,
                              void* d_out, int out_size)
{
    const int*   x      = (const int*)  d_in[0];  // [8,100,64,32] int32
    const float* W      = (const float*)d_in[1];  // [32000,128]  f32
    const float* w_pred = (const float*)d_in[2];  // [1,128]      f32
    const float* b_pred = (const float*)d_in[3];  // [1]          f32
    float*       out    = (float*)d_out;          // [8,100,64]   f32

    // 1) Convert W to fp16 scratch (8 elems per thread).
    const int n8 = VOCAB * DIMS / 8;               // 512,000
    convert_w_kernel<<<(n8 + 255) / 256, 256>>>(W, n8);

    // 2) Gather + pool + GELU + dot.
    const int n_cells = out_size;                  // 51200
    const int blocks = (n_cells + 7) / 8;          // 8 warps / block
    gelu_avg_embed_kernel<<<blocks, 256>>>(x, w_pred, b_pred, out, n_cells);
}